// round 9
// baseline (speedup 1.0000x reference)
#include <cuda_runtime.h>
#include <cstdint>

#define QQ 500
#define CDIM 256
#define ROWS 64              // rows per CTA (8 queries x 8 samples, flattened globally)
#define NCTAS 500            // 32000 / 64
#define MEMROWS 8500
#define CHUNK 64             // c-channels per pipeline chunk

// dynamic smem offsets (bytes)
#define OFF_A   0                    // emb rows 0..31:  c*128, 32 KB   (reused as h rows 0..31)
#define OFF_B   (32768 + 16)         // emb rows 32..63: c*128, 32 KB, +16B bank skew (h rows 32..63)
#define OFF_W2T 65568                // 4 x 260 f32 (1040 B stride)
#define OFF_SPT 69728                // 64 x float2
#define OFF_IDX 70240                // 64 x int4
#define OFF_WGT 71264                // 64 x float4
#define SMEM_TOTAL 72288

__device__ __align__(16) unsigned long long g_w1d[CDIM * CDIM];   // (w,w) dup pairs, 512 KB

__device__ __forceinline__ unsigned long long ffma2(unsigned long long a,
                                                    unsigned long long b,
                                                    unsigned long long c) {
    unsigned long long d;
    asm("fma.rn.f32x2 %0, %1, %2, %3;" : "=l"(d) : "l"(a), "l"(b), "l"(c));
    return d;
}
__device__ __forceinline__ unsigned long long pack2(float lo, float hi) {
    unsigned long long r;
    asm("mov.b64 %0, {%1, %2};" : "=l"(r) : "f"(lo), "f"(hi));
    return r;
}
__device__ __forceinline__ void unpack2(unsigned long long v, float& lo, float& hi) {
    asm("mov.b64 {%0, %1}, %2;" : "=f"(lo), "=f"(hi) : "l"(v));
}
__device__ __forceinline__ float tanh_fast(float x) {
    float y; asm("tanh.approx.f32 %0, %1;" : "=f"(y) : "f"(x)); return y;
}

// one-time: W1[c][j] -> (w,w) pairs
__global__ void prep_w1d_kernel(const float* __restrict__ W1) {
    const int idx = blockIdx.x * 256 + threadIdx.x;   // 65536 elements
    const float v = W1[idx];
    g_w1d[idx] = pack2(v, v);
}

__global__ void __launch_bounds__(256, 2)
decoder_fused_kernel(const float* __restrict__ ref_polys,
                     const int*   __restrict__ ref_levels,
                     const float* __restrict__ memory,
                     const float* __restrict__ b1,
                     const float* __restrict__ W2,
                     const float* __restrict__ b2,
                     float*       __restrict__ out)
{
    extern __shared__ __align__(16) char sb[];
    const int tid = threadIdx.x;
    const int bid = blockIdx.x;

    // ---- Phase 1a: per-row sampling point + bilinear corner setup (64 threads) ----
    if (tid < ROWS) {
        const int gr = bid * ROWS + tid;        // global row, (bq, s) flattened
        const int bq = gr >> 3;
        const int s  = gr & 7;
        const float* rp = ref_polys + (size_t)bq * 8;
        const float lam = (float)s * (1.0f / 7.0f);
        const float sx = 2.0f * ((((rp[0] * lam + rp[1]) * lam + rp[2]) * lam + rp[3]) - 0.5f);
        const float sy = 2.0f * ((((rp[4] * lam + rp[5]) * lam + rp[6]) * lam + rp[7]) - 0.5f);
        ((float2*)(sb + OFF_SPT))[tid] = make_float2(sx, sy);

        const int lvl = ref_levels[bq];
        const int hs_tab[4] = {80, 40, 20, 10};
        const int st_tab[4] = {0, 6400, 8000, 8400};
        const int W  = hs_tab[lvl];
        const int st = st_tab[lvl];
        const int b  = bq / QQ;

        const float gx = (sx + 1.0f) * 0.5f * (float)W - 0.5f;
        const float gy = (sy + 1.0f) * 0.5f * (float)W - 0.5f;
        const float x0f = floorf(gx), y0f = floorf(gy);
        const float fx = gx - x0f, fy = gy - y0f;
        const int x0 = (int)x0f, y0 = (int)y0f;
        const int base = b * MEMROWS + st;
        int4 ix; float4 wv;
        int* ixp = (int*)&ix; float* wvp = (float*)&wv;
        #pragma unroll
        for (int k = 0; k < 4; k++) {
            const int xi = x0 + (k & 1);
            const int yi = y0 + (k >> 1);
            const bool v = (xi >= 0) && (xi < W) && (yi >= 0) && (yi < W);
            ixp[k] = v ? (base + yi * W + xi) : -1;
            const float wx = (k & 1) ? fx : 1.0f - fx;
            const float wy = (k >> 1) ? fy : 1.0f - fy;
            wvp[k] = wx * wy;
        }
        ((int4*)(sb + OFF_IDX))[tid] = ix;
        ((float4*)(sb + OFF_WGT))[tid] = wv;
    }
    // ---- Phase 1b: W2^T into smem, 1040-byte row stride ----
    #pragma unroll
    for (int i = tid; i < 4 * CDIM; i += 256)
        *(float*)(sb + OFF_W2T + (i & 3) * 1040 + (i >> 2) * 4) = W2[i];
    __syncthreads();

    // Gather one chunk: thread = (row-quarter rq, c-within-chunk). 16 rows x 4 corners.
    const int g_c64 = tid & 63;
    const int g_rq  = tid >> 6;            // rows 16*rq .. 16*rq+15
    #define GATHER_CHUNK(K)                                                              \
    do {                                                                                 \
        const int c_ = (K) * CHUNK + g_c64;                                              \
        const uint32_t csw_ = (uint32_t)(c_ & 7);                                        \
        _Pragma("unroll")                                                                \
        for (int r4_ = 0; r4_ < 4; r4_++) {                                              \
            const int g_ = g_rq * 4 + r4_;             /* granule 0..15 */               \
            float4 buf_;                                                                 \
            float* bf_ = (float*)&buf_;                                                  \
            _Pragma("unroll")                                                            \
            for (int rr_ = 0; rr_ < 4; rr_++) {                                          \
                const int r_ = g_ * 4 + rr_;                                             \
                const int4   ix_ = ((const int4*)(sb + OFF_IDX))[r_];                    \
                const float4 wv_ = ((const float4*)(sb + OFF_WGT))[r_];                  \
                float acc_ = 0.0f;                                                       \
                if (ix_.x >= 0) acc_ += wv_.x * __ldg(memory + (size_t)ix_.x * CDIM + c_); \
                if (ix_.y >= 0) acc_ += wv_.y * __ldg(memory + (size_t)ix_.y * CDIM + c_); \
                if (ix_.z >= 0) acc_ += wv_.z * __ldg(memory + (size_t)ix_.z * CDIM + c_); \
                if (ix_.w >= 0) acc_ += wv_.w * __ldg(memory + (size_t)ix_.w * CDIM + c_); \
                bf_[rr_] = acc_;                                                         \
            }                                                                            \
            const uint32_t half_ = (uint32_t)(g_ >> 3);                                  \
            const uint32_t gsl_  = ((uint32_t)(g_ & 7)) ^ csw_;                          \
            *(float4*)(sb + half_ * (uint32_t)OFF_B + ((uint32_t)c_ << 7) + (gsl_ << 4)) = buf_; \
        }                                                                                \
    } while (0)

    // ---- prologue: gather chunk 0 ----
    GATHER_CHUNK(0);
    __syncthreads();

    // ---- Phase 3: layer-1 GEMM (8 rows x 8 cols per thread) pipelined with gather ----
    const int lane = tid & 31;
    const int wid  = tid >> 5;
    const int rb   = lane & 7;                  // rows rb*8 .. rb*8+7
    const int e    = lane >> 3;                 // 0..3
    const int cb   = wid * 4 + e;               // 0..31
    const int j0   = cb * 8;

    unsigned long long acc[4][8];               // [rowpair][col]
    {
        const float4 b1a = __ldg((const float4*)(b1 + j0));
        const float4 b1b = __ldg((const float4*)(b1 + j0 + 4));
        #pragma unroll
        for (int rp = 0; rp < 4; rp++) {
            acc[rp][0] = pack2(b1a.x, b1a.x); acc[rp][1] = pack2(b1a.y, b1a.y);
            acc[rp][2] = pack2(b1a.z, b1a.z); acc[rp][3] = pack2(b1a.w, b1a.w);
            acc[rp][4] = pack2(b1b.x, b1b.x); acc[rp][5] = pack2(b1b.y, b1b.y);
            acc[rp][6] = pack2(b1b.z, b1b.z); acc[rp][7] = pack2(b1b.w, b1b.w);
        }
    }

    const char* ebase = sb + (uint32_t)(rb >> 2) * (uint32_t)OFF_B;
    const uint32_t rbf = ((uint32_t)(rb & 3)) << 5;
    const unsigned long long* w1d = g_w1d + j0;

    #pragma unroll 1
    for (int k = 0; k < 4; k++) {
        const int cbeg = k * CHUNK;
        #pragma unroll 1
        for (int c0 = cbeg; c0 < cbeg + CHUNK; c0 += 8) {
            #pragma unroll
            for (int cc = 0; cc < 8; cc++) {
                const int c = c0 + cc;
                const ulonglong2* wp = (const ulonglong2*)(w1d + (size_t)c * CDIM);
                const ulonglong2 wd0 = wp[0];     // (w_j0,w_j0),(w_j0+1,w_j0+1)
                const ulonglong2 wd1 = wp[1];
                const ulonglong2 wd2 = wp[2];
                const ulonglong2 wd3 = wp[3];
                const uint32_t v0 = rbf ^ ((uint32_t)cc << 4);
                const char* ep = ebase + ((uint32_t)c << 7);
                const ulonglong2 eA = *(const ulonglong2*)(ep + v0);
                const ulonglong2 eB = *(const ulonglong2*)(ep + (v0 ^ 16u));
                acc[0][0] = ffma2(eA.x, wd0.x, acc[0][0]); acc[0][1] = ffma2(eA.x, wd0.y, acc[0][1]);
                acc[0][2] = ffma2(eA.x, wd1.x, acc[0][2]); acc[0][3] = ffma2(eA.x, wd1.y, acc[0][3]);
                acc[0][4] = ffma2(eA.x, wd2.x, acc[0][4]); acc[0][5] = ffma2(eA.x, wd2.y, acc[0][5]);
                acc[0][6] = ffma2(eA.x, wd3.x, acc[0][6]); acc[0][7] = ffma2(eA.x, wd3.y, acc[0][7]);
                acc[1][0] = ffma2(eA.y, wd0.x, acc[1][0]); acc[1][1] = ffma2(eA.y, wd0.y, acc[1][1]);
                acc[1][2] = ffma2(eA.y, wd1.x, acc[1][2]); acc[1][3] = ffma2(eA.y, wd1.y, acc[1][3]);
                acc[1][4] = ffma2(eA.y, wd2.x, acc[1][4]); acc[1][5] = ffma2(eA.y, wd2.y, acc[1][5]);
                acc[1][6] = ffma2(eA.y, wd3.x, acc[1][6]); acc[1][7] = ffma2(eA.y, wd3.y, acc[1][7]);
                acc[2][0] = ffma2(eB.x, wd0.x, acc[2][0]); acc[2][1] = ffma2(eB.x, wd0.y, acc[2][1]);
                acc[2][2] = ffma2(eB.x, wd1.x, acc[2][2]); acc[2][3] = ffma2(eB.x, wd1.y, acc[2][3]);
                acc[2][4] = ffma2(eB.x, wd2.x, acc[2][4]); acc[2][5] = ffma2(eB.x, wd2.y, acc[2][5]);
                acc[2][6] = ffma2(eB.x, wd3.x, acc[2][6]); acc[2][7] = ffma2(eB.x, wd3.y, acc[2][7]);
                acc[3][0] = ffma2(eB.y, wd0.x, acc[3][0]); acc[3][1] = ffma2(eB.y, wd0.y, acc[3][1]);
                acc[3][2] = ffma2(eB.y, wd1.x, acc[3][2]); acc[3][3] = ffma2(eB.y, wd1.y, acc[3][3]);
                acc[3][4] = ffma2(eB.y, wd2.x, acc[3][4]); acc[3][5] = ffma2(eB.y, wd2.y, acc[3][5]);
                acc[3][6] = ffma2(eB.y, wd3.x, acc[3][6]); acc[3][7] = ffma2(eB.y, wd3.y, acc[3][7]);
            }
        }
        // gather next chunk while co-resident warps still run FFMA2 streams
        if (k < 3) {
            switch (k) {
                case 0: GATHER_CHUNK(1); break;
                case 1: GATHER_CHUNK(2); break;
                default: GATHER_CHUNK(3); break;
            }
        }
        __syncthreads();
    }

    // ---- tanh + store h (emb buffer reuse; all GEMM reads done at last sync) ----
    {
        #pragma unroll
        for (int rp = 0; rp < 4; rp++) {
            float lo[8], hi[8];
            #pragma unroll
            for (int kk = 0; kk < 8; kk++) unpack2(acc[rp][kk], lo[kk], hi[kk]);
            #pragma unroll
            for (int t = 0; t < 2; t++) {
                const float* v = t ? hi : lo;
                const int row = rb * 8 + 2 * rp + t;
                char* hb = sb + (((uint32_t)row & 31u) << 10)
                              + ((uint32_t)(row >> 5)) * (uint32_t)OFF_B;
                const uint32_t sw = ((uint32_t)(row & 7)) << 4;
                *(float4*)(hb + (((uint32_t)(j0 * 4)) ^ sw)) =
                    make_float4(tanh_fast(v[0]), tanh_fast(v[1]),
                                tanh_fast(v[2]), tanh_fast(v[3]));
                *(float4*)(hb + (((uint32_t)(j0 * 4 + 16)) ^ sw)) =
                    make_float4(tanh_fast(v[4]), tanh_fast(v[5]),
                                tanh_fast(v[6]), tanh_fast(v[7]));
            }
        }
    }
    __syncthreads();

    // ---- Phase 4: layer 2 + tanh epilogue (thread = (row, p)) ----
    {
        const int r = tid >> 2;            // 0..63
        const int p = tid & 3;             // 0..3
        const char* hrow = sb + (((uint32_t)r & 31u) << 10)
                              + ((uint32_t)(r >> 5)) * (uint32_t)OFF_B;
        const uint32_t sw = ((uint32_t)(r & 7)) << 4;
        const char* w2p = sb + OFF_W2T + p * 1040;

        unsigned long long a0 = 0, a1 = 0;
        #pragma unroll 8
        for (int g = 0; g < 64; g++) {
            const uint32_t off = (uint32_t)g << 4;
            const ulonglong2 hv = *(const ulonglong2*)(hrow + (off ^ sw));
            const ulonglong2 wv = *(const ulonglong2*)(w2p + off);
            a0 = ffma2(hv.x, wv.x, a0);
            a1 = ffma2(hv.y, wv.y, a1);
        }
        float l0, h0, l1, h1;
        unpack2(a0, l0, h0);
        unpack2(a1, l1, h1);
        float sum = (l0 + h0) + (l1 + h1) + __ldg(b2 + p);
        const float off = 0.077f * tanh_fast(sum);
        const float2 spt = ((const float2*)(sb + OFF_SPT))[r];
        const int gr = bid * ROWS + r;
        out[(size_t)gr * 4 + p] = off + ((p & 1) ? spt.y : spt.x);
    }
}

extern "C" void kernel_launch(void* const* d_in, const int* in_sizes, int n_in,
                              void* d_out, int out_size)
{
    const float* ref_polys  = (const float*)d_in[0];
    const int*   ref_levels = (const int*)  d_in[1];
    const float* memory     = (const float*)d_in[2];
    const float* W1         = (const float*)d_in[3];
    const float* b1         = (const float*)d_in[4];
    const float* W2         = (const float*)d_in[5];
    const float* b2         = (const float*)d_in[6];
    float* out = (float*)d_out;

    cudaFuncSetAttribute(decoder_fused_kernel,
                         cudaFuncAttributeMaxDynamicSharedMemorySize, SMEM_TOTAL);

    prep_w1d_kernel<<<CDIM, 256>>>(W1);
    decoder_fused_kernel<<<NCTAS, 256, SMEM_TOTAL>>>(ref_polys, ref_levels, memory,
                                                     b1, W2, b2, out);
}

// round 10
// speedup vs baseline: 1.2922x; 1.2922x over previous
#include <cuda_runtime.h>
#include <cstdint>

#define QQ 500
#define CDIM 256
#define ROWS 64              // rows per CTA in GEMM kernel
#define NCTAS 500            // 32000 / 64
#define NROWS_TOTAL 32000
#define MEMROWS 8500

// dynamic smem offsets (bytes) — GEMM kernel
#define OFF_A   0                    // emb rows 0..31:  c*128, 32 KB   (reused as h rows 0..31)
#define OFF_B   (32768 + 16)         // emb rows 32..63: c*128, 32 KB, +16B bank skew (h rows 32..63)
#define OFF_W2T 65568                // 4 x 260 f32 (1040 B stride)
#define OFF_SPT 69728                // 64 x float2
#define SMEM_TOTAL 70240

__device__ __align__(16) float g_emb[NROWS_TOTAL * CDIM];   // 32 MB scratch, row-major [gr][c]

__device__ __forceinline__ unsigned long long ffma2(unsigned long long a,
                                                    unsigned long long b,
                                                    unsigned long long c) {
    unsigned long long d;
    asm("fma.rn.f32x2 %0, %1, %2, %3;" : "=l"(d) : "l"(a), "l"(b), "l"(c));
    return d;
}
__device__ __forceinline__ unsigned long long pack2(float lo, float hi) {
    unsigned long long r;
    asm("mov.b64 %0, {%1, %2};" : "=l"(r) : "f"(lo), "f"(hi));
    return r;
}
__device__ __forceinline__ void unpack2(unsigned long long v, float& lo, float& hi) {
    asm("mov.b64 {%0, %1}, %2;" : "=f"(lo), "=f"(hi) : "l"(v));
}
__device__ __forceinline__ float tanh_fast(float x) {
    float y; asm("tanh.approx.f32 %0, %1;" : "=f"(y) : "f"(x)); return y;
}

// ---------------- Kernel A: bilinear gather -> g_emb (row-major, coalesced) ----------------
// thread = (row, 4 channels). 8000 CTAs x 256 thr; each CTA covers 4 rows.
__global__ void __launch_bounds__(256)
gather_kernel(const float* __restrict__ ref_polys,
              const int*   __restrict__ ref_levels,
              const float* __restrict__ memory)
{
    const int t   = blockIdx.x * 256 + threadIdx.x;
    const int row = t >> 6;               // global row 0..31999
    const int c   = (t & 63) << 2;        // channel base

    const int bq = row >> 3;
    const int s  = row & 7;
    const float* rp = ref_polys + (size_t)bq * 8;
    const float lam = (float)s * (1.0f / 7.0f);
    const float sx = 2.0f * ((((rp[0] * lam + rp[1]) * lam + rp[2]) * lam + rp[3]) - 0.5f);
    const float sy = 2.0f * ((((rp[4] * lam + rp[5]) * lam + rp[6]) * lam + rp[7]) - 0.5f);

    const int lvl = ref_levels[bq];
    const int hs_tab[4] = {80, 40, 20, 10};
    const int st_tab[4] = {0, 6400, 8000, 8400};
    const int W  = hs_tab[lvl];
    const int st = st_tab[lvl];
    const int b  = bq / QQ;

    const float gx = (sx + 1.0f) * 0.5f * (float)W - 0.5f;
    const float gy = (sy + 1.0f) * 0.5f * (float)W - 0.5f;
    const float x0f = floorf(gx), y0f = floorf(gy);
    const float fx = gx - x0f, fy = gy - y0f;
    const int x0 = (int)x0f, y0 = (int)y0f;
    const int base = b * MEMROWS + st;

    float4 acc = make_float4(0.f, 0.f, 0.f, 0.f);
    #pragma unroll
    for (int k = 0; k < 4; k++) {
        const int xi = x0 + (k & 1);
        const int yi = y0 + (k >> 1);
        if ((xi >= 0) && (xi < W) && (yi >= 0) && (yi < W)) {
            const float wx = (k & 1) ? fx : 1.0f - fx;
            const float wy = (k >> 1) ? fy : 1.0f - fy;
            const float w  = wx * wy;
            const float4 v = __ldg((const float4*)(memory + (size_t)(base + yi * W + xi) * CDIM + c));
            acc.x += w * v.x; acc.y += w * v.y; acc.z += w * v.z; acc.w += w * v.w;
        }
    }
    *(float4*)(g_emb + (size_t)row * CDIM + c) = acc;
}

// ---------------- Kernel B: staging + layer-1 GEMM + MLP epilogue (R6 structure) ----------------
__global__ void __launch_bounds__(256, 2)
decoder_gemm_kernel(const float* __restrict__ ref_polys,
                    const float* __restrict__ W1,
                    const float* __restrict__ b1,
                    const float* __restrict__ W2,
                    const float* __restrict__ b2,
                    float*       __restrict__ out)
{
    extern __shared__ __align__(16) char sb[];
    const int tid = threadIdx.x;
    const int bid = blockIdx.x;

    // ---- sampling points for epilogue (64 threads; cheap poly re-eval) ----
    if (tid < ROWS) {
        const int gr = bid * ROWS + tid;
        const int bq = gr >> 3;
        const int s  = gr & 7;
        const float* rp = ref_polys + (size_t)bq * 8;
        const float lam = (float)s * (1.0f / 7.0f);
        const float sx = 2.0f * ((((rp[0] * lam + rp[1]) * lam + rp[2]) * lam + rp[3]) - 0.5f);
        const float sy = 2.0f * ((((rp[4] * lam + rp[5]) * lam + rp[6]) * lam + rp[7]) - 0.5f);
        ((float2*)(sb + OFF_SPT))[tid] = make_float2(sx, sy);
    }
    // ---- W2^T into smem, 1040-byte row stride ----
    #pragma unroll
    for (int i = tid; i < 4 * CDIM; i += 256)
        *(float*)(sb + OFF_W2T + (i & 3) * 1040 + (i >> 2) * 4) = W2[i];

    // ---- stage emb tile: g_emb row-major -> swizzled smem layout (thread = channel c) ----
    {
        const int c = tid;
        const uint32_t csw = (uint32_t)(c & 7);
        const float* src = g_emb + (size_t)bid * ROWS * CDIM + c;
        #pragma unroll 4
        for (int g = 0; g < 16; g++) {              // granule = 4 rows
            float4 buf;
            float* bf = (float*)&buf;
            #pragma unroll
            for (int rr = 0; rr < 4; rr++)
                bf[rr] = __ldg(src + (size_t)(g * 4 + rr) * CDIM);   // coalesced across c
            const uint32_t half = (uint32_t)(g >> 3);
            const uint32_t gsl  = ((uint32_t)(g & 7)) ^ csw;
            *(float4*)(sb + half * (uint32_t)OFF_B + ((uint32_t)c << 7) + (gsl << 4)) = buf;
        }
    }
    __syncthreads();

    // ---- layer-1 GEMM, thread tile = 8 rows x 8 cols (R6 verified) ----
    const int lane = tid & 31;
    const int wid  = tid >> 5;
    const int rb   = lane & 7;                  // rows rb*8 .. rb*8+7
    const int e    = lane >> 3;                 // 0..3
    const int cb   = wid * 4 + e;               // 0..31
    const int j0   = cb * 8;

    unsigned long long acc[4][8];               // [rowpair][col]
    {
        const float4 b1a = __ldg((const float4*)(b1 + j0));
        const float4 b1b = __ldg((const float4*)(b1 + j0 + 4));
        #pragma unroll
        for (int rp = 0; rp < 4; rp++) {
            acc[rp][0] = pack2(b1a.x, b1a.x); acc[rp][1] = pack2(b1a.y, b1a.y);
            acc[rp][2] = pack2(b1a.z, b1a.z); acc[rp][3] = pack2(b1a.w, b1a.w);
            acc[rp][4] = pack2(b1b.x, b1b.x); acc[rp][5] = pack2(b1b.y, b1b.y);
            acc[rp][6] = pack2(b1b.z, b1b.z); acc[rp][7] = pack2(b1b.w, b1b.w);
        }
    }

    const char* ebase = sb + (uint32_t)(rb >> 2) * (uint32_t)OFF_B;
    const uint32_t rbf = ((uint32_t)(rb & 3)) << 5;
    const float* w1p = W1 + j0;

    for (int c0 = 0; c0 < CDIM; c0 += 8) {
        #pragma unroll
        for (int cc = 0; cc < 8; cc++) {
            const int c = c0 + cc;
            const float4 wA = __ldg((const float4*)(w1p + (size_t)c * CDIM));
            const float4 wB = __ldg((const float4*)(w1p + (size_t)c * CDIM + 4));
            const uint32_t v0 = rbf ^ ((uint32_t)cc << 4);
            const char* ep = ebase + ((uint32_t)c << 7);
            const ulonglong2 eA = *(const ulonglong2*)(ep + v0);
            const ulonglong2 eB = *(const ulonglong2*)(ep + (v0 ^ 16u));
            const unsigned long long w0 = pack2(wA.x, wA.x);
            const unsigned long long w1v = pack2(wA.y, wA.y);
            const unsigned long long w2v = pack2(wA.z, wA.z);
            const unsigned long long w3 = pack2(wA.w, wA.w);
            const unsigned long long w4 = pack2(wB.x, wB.x);
            const unsigned long long w5 = pack2(wB.y, wB.y);
            const unsigned long long w6 = pack2(wB.z, wB.z);
            const unsigned long long w7 = pack2(wB.w, wB.w);
            acc[0][0] = ffma2(eA.x, w0, acc[0][0]); acc[0][1] = ffma2(eA.x, w1v, acc[0][1]);
            acc[0][2] = ffma2(eA.x, w2v, acc[0][2]); acc[0][3] = ffma2(eA.x, w3, acc[0][3]);
            acc[0][4] = ffma2(eA.x, w4, acc[0][4]); acc[0][5] = ffma2(eA.x, w5, acc[0][5]);
            acc[0][6] = ffma2(eA.x, w6, acc[0][6]); acc[0][7] = ffma2(eA.x, w7, acc[0][7]);
            acc[1][0] = ffma2(eA.y, w0, acc[1][0]); acc[1][1] = ffma2(eA.y, w1v, acc[1][1]);
            acc[1][2] = ffma2(eA.y, w2v, acc[1][2]); acc[1][3] = ffma2(eA.y, w3, acc[1][3]);
            acc[1][4] = ffma2(eA.y, w4, acc[1][4]); acc[1][5] = ffma2(eA.y, w5, acc[1][5]);
            acc[1][6] = ffma2(eA.y, w6, acc[1][6]); acc[1][7] = ffma2(eA.y, w7, acc[1][7]);
            acc[2][0] = ffma2(eB.x, w0, acc[2][0]); acc[2][1] = ffma2(eB.x, w1v, acc[2][1]);
            acc[2][2] = ffma2(eB.x, w2v, acc[2][2]); acc[2][3] = ffma2(eB.x, w3, acc[2][3]);
            acc[2][4] = ffma2(eB.x, w4, acc[2][4]); acc[2][5] = ffma2(eB.x, w5, acc[2][5]);
            acc[2][6] = ffma2(eB.x, w6, acc[2][6]); acc[2][7] = ffma2(eB.x, w7, acc[2][7]);
            acc[3][0] = ffma2(eB.y, w0, acc[3][0]); acc[3][1] = ffma2(eB.y, w1v, acc[3][1]);
            acc[3][2] = ffma2(eB.y, w2v, acc[3][2]); acc[3][3] = ffma2(eB.y, w3, acc[3][3]);
            acc[3][4] = ffma2(eB.y, w4, acc[3][4]); acc[3][5] = ffma2(eB.y, w5, acc[3][5]);
            acc[3][6] = ffma2(eB.y, w6, acc[3][6]); acc[3][7] = ffma2(eB.y, w7, acc[3][7]);
        }
    }

    __syncthreads();   // emb reads complete before buffer reuse as h

    // ---- tanh + store h ----
    {
        #pragma unroll
        for (int rp = 0; rp < 4; rp++) {
            float lo[8], hi[8];
            #pragma unroll
            for (int kk = 0; kk < 8; kk++) unpack2(acc[rp][kk], lo[kk], hi[kk]);
            #pragma unroll
            for (int t = 0; t < 2; t++) {
                const float* v = t ? hi : lo;
                const int row = rb * 8 + 2 * rp + t;
                char* hb = sb + (((uint32_t)row & 31u) << 10)
                              + ((uint32_t)(row >> 5)) * (uint32_t)OFF_B;
                const uint32_t sw = ((uint32_t)(row & 7)) << 4;
                *(float4*)(hb + (((uint32_t)(j0 * 4)) ^ sw)) =
                    make_float4(tanh_fast(v[0]), tanh_fast(v[1]),
                                tanh_fast(v[2]), tanh_fast(v[3]));
                *(float4*)(hb + (((uint32_t)(j0 * 4 + 16)) ^ sw)) =
                    make_float4(tanh_fast(v[4]), tanh_fast(v[5]),
                                tanh_fast(v[6]), tanh_fast(v[7]));
            }
        }
    }
    __syncthreads();

    // ---- layer 2 + tanh epilogue (thread = (row, p)) ----
    {
        const int r = tid >> 2;            // 0..63
        const int p = tid & 3;             // 0..3
        const char* hrow = sb + (((uint32_t)r & 31u) << 10)
                              + ((uint32_t)(r >> 5)) * (uint32_t)OFF_B;
        const uint32_t sw = ((uint32_t)(r & 7)) << 4;
        const char* w2p = sb + OFF_W2T + p * 1040;

        unsigned long long a0 = 0, a1 = 0;
        #pragma unroll 8
        for (int g = 0; g < 64; g++) {
            const uint32_t off = (uint32_t)g << 4;
            const ulonglong2 hv = *(const ulonglong2*)(hrow + (off ^ sw));
            const ulonglong2 wv = *(const ulonglong2*)(w2p + off);
            a0 = ffma2(hv.x, wv.x, a0);
            a1 = ffma2(hv.y, wv.y, a1);
        }
        float l0, h0, l1, h1;
        unpack2(a0, l0, h0);
        unpack2(a1, l1, h1);
        float sum = (l0 + h0) + (l1 + h1) + __ldg(b2 + p);
        const float off = 0.077f * tanh_fast(sum);
        const float2 spt = ((const float2*)(sb + OFF_SPT))[r];
        const int gr = bid * ROWS + r;
        out[(size_t)gr * 4 + p] = off + ((p & 1) ? spt.y : spt.x);
    }
}

extern "C" void kernel_launch(void* const* d_in, const int* in_sizes, int n_in,
                              void* d_out, int out_size)
{
    const float* ref_polys  = (const float*)d_in[0];
    const int*   ref_levels = (const int*)  d_in[1];
    const float* memory     = (const float*)d_in[2];
    const float* W1         = (const float*)d_in[3];
    const float* b1         = (const float*)d_in[4];
    const float* W2         = (const float*)d_in[5];
    const float* b2         = (const float*)d_in[6];
    float* out = (float*)d_out;

    cudaFuncSetAttribute(decoder_gemm_kernel,
                         cudaFuncAttributeMaxDynamicSharedMemorySize, SMEM_TOTAL);

    gather_kernel<<<NROWS_TOTAL / 4, 256>>>(ref_polys, ref_levels, memory);
    decoder_gemm_kernel<<<NCTAS, 256, SMEM_TOTAL>>>(ref_polys, W1, b1, W2, b2, out);
}

// round 11
// speedup vs baseline: 1.3897x; 1.0754x over previous
#include <cuda_runtime.h>
#include <cstdint>

#define QQ 500
#define CDIM 256
#define ROWS 64              // rows per CTA in GEMM kernel
#define NCTAS 500            // 32000 / 64
#define NROWS_TOTAL 32000
#define MEMROWS 8500
#define WBLK 16              // c-rows per W1 pipeline block
#define NBLK (CDIM / WBLK)   // 16

// dynamic smem offsets (bytes) — GEMM kernel
#define OFF_A   0                    // emb rows 0..31:  c*128, 32 KB   (reused as h rows 0..31)
#define OFF_B   (32768 + 16)         // emb rows 32..63: c*128, 32 KB, +16B bank skew (h rows 32..63)
#define OFF_W2T 65568                // 4 x 260 f32 (1040 B stride)
#define OFF_SPT 69728                // 64 x float2
#define OFF_W1  70272                // 2 x 16 KB W1 double buffer (128B aligned)
#define SMEM_TOTAL (70272 + 32768)   // 103040

__device__ __align__(16) float g_emb[NROWS_TOTAL * CDIM];   // 32 MB scratch, row-major [gr][c]

__device__ __forceinline__ unsigned long long ffma2(unsigned long long a,
                                                    unsigned long long b,
                                                    unsigned long long c) {
    unsigned long long d;
    asm("fma.rn.f32x2 %0, %1, %2, %3;" : "=l"(d) : "l"(a), "l"(b), "l"(c));
    return d;
}
__device__ __forceinline__ unsigned long long pack2(float lo, float hi) {
    unsigned long long r;
    asm("mov.b64 %0, {%1, %2};" : "=l"(r) : "f"(lo), "f"(hi));
    return r;
}
__device__ __forceinline__ void unpack2(unsigned long long v, float& lo, float& hi) {
    asm("mov.b64 {%0, %1}, %2;" : "=f"(lo), "=f"(hi) : "l"(v));
}
__device__ __forceinline__ float tanh_fast(float x) {
    float y; asm("tanh.approx.f32 %0, %1;" : "=f"(y) : "f"(x)); return y;
}
__device__ __forceinline__ uint32_t smem_u32(const void* p) {
    uint32_t a;
    asm("{ .reg .u64 t; cvta.to.shared.u64 t, %1; cvt.u32.u64 %0, t; }" : "=r"(a) : "l"(p));
    return a;
}

// ---------------- Kernel A: bilinear gather -> g_emb (row-major, coalesced) ----------------
__global__ void __launch_bounds__(256)
gather_kernel(const float* __restrict__ ref_polys,
              const int*   __restrict__ ref_levels,
              const float* __restrict__ memory)
{
    const int t   = blockIdx.x * 256 + threadIdx.x;
    const int row = t >> 6;               // global row 0..31999
    const int c   = (t & 63) << 2;        // channel base

    const int bq = row >> 3;
    const int s  = row & 7;
    const float* rp = ref_polys + (size_t)bq * 8;
    const float lam = (float)s * (1.0f / 7.0f);
    const float sx = 2.0f * ((((rp[0] * lam + rp[1]) * lam + rp[2]) * lam + rp[3]) - 0.5f);
    const float sy = 2.0f * ((((rp[4] * lam + rp[5]) * lam + rp[6]) * lam + rp[7]) - 0.5f);

    const int lvl = ref_levels[bq];
    const int hs_tab[4] = {80, 40, 20, 10};
    const int st_tab[4] = {0, 6400, 8000, 8400};
    const int W  = hs_tab[lvl];
    const int st = st_tab[lvl];
    const int b  = bq / QQ;

    const float gx = (sx + 1.0f) * 0.5f * (float)W - 0.5f;
    const float gy = (sy + 1.0f) * 0.5f * (float)W - 0.5f;
    const float x0f = floorf(gx), y0f = floorf(gy);
    const float fx = gx - x0f, fy = gy - y0f;
    const int x0 = (int)x0f, y0 = (int)y0f;
    const int base = b * MEMROWS + st;

    float4 acc = make_float4(0.f, 0.f, 0.f, 0.f);
    #pragma unroll
    for (int k = 0; k < 4; k++) {
        const int xi = x0 + (k & 1);
        const int yi = y0 + (k >> 1);
        if ((xi >= 0) && (xi < W) && (yi >= 0) && (yi < W)) {
            const float wx = (k & 1) ? fx : 1.0f - fx;
            const float wy = (k >> 1) ? fy : 1.0f - fy;
            const float w  = wx * wy;
            const float4 v = __ldg((const float4*)(memory + (size_t)(base + yi * W + xi) * CDIM + c));
            acc.x += w * v.x; acc.y += w * v.y; acc.z += w * v.z; acc.w += w * v.w;
        }
    }
    *(float4*)(g_emb + (size_t)row * CDIM + c) = acc;
}

// ---------------- Kernel B: staging + layer-1 GEMM (cp.async W1 pipeline) + MLP epilogue ----
__global__ void __launch_bounds__(256, 2)
decoder_gemm_kernel(const float* __restrict__ ref_polys,
                    const float* __restrict__ W1,
                    const float* __restrict__ b1,
                    const float* __restrict__ W2,
                    const float* __restrict__ b2,
                    float*       __restrict__ out)
{
    extern __shared__ __align__(16) char sb[];
    const int tid = threadIdx.x;
    const int bid = blockIdx.x;
    const uint32_t w1s = smem_u32(sb) + OFF_W1;

    // ---- kick off W1 block 0 immediately (overlaps everything below) ----
    {
        const float* src = W1;
        #pragma unroll
        for (int i = 0; i < 4; i++)
            asm volatile("cp.async.cg.shared.global [%0], [%1], 16;"
                :: "r"(w1s + (uint32_t)(tid + i * 256) * 16u),
                   "l"(src + (size_t)(tid + i * 256) * 4) : "memory");
        asm volatile("cp.async.commit_group;" ::: "memory");
    }

    // ---- sampling points for epilogue (64 threads) ----
    if (tid < ROWS) {
        const int gr = bid * ROWS + tid;
        const int bq = gr >> 3;
        const int s  = gr & 7;
        const float* rp = ref_polys + (size_t)bq * 8;
        const float lam = (float)s * (1.0f / 7.0f);
        const float sx = 2.0f * ((((rp[0] * lam + rp[1]) * lam + rp[2]) * lam + rp[3]) - 0.5f);
        const float sy = 2.0f * ((((rp[4] * lam + rp[5]) * lam + rp[6]) * lam + rp[7]) - 0.5f);
        ((float2*)(sb + OFF_SPT))[tid] = make_float2(sx, sy);
    }
    // ---- W2^T into smem, 1040-byte row stride ----
    #pragma unroll
    for (int i = tid; i < 4 * CDIM; i += 256)
        *(float*)(sb + OFF_W2T + (i & 3) * 1040 + (i >> 2) * 4) = W2[i];

    // ---- stage emb tile: g_emb row-major -> swizzled smem layout (thread = channel c) ----
    {
        const int c = tid;
        const uint32_t csw = (uint32_t)(c & 7);
        const float* src = g_emb + (size_t)bid * ROWS * CDIM + c;
        #pragma unroll 4
        for (int g = 0; g < 16; g++) {              // granule = 4 rows
            float4 buf;
            float* bf = (float*)&buf;
            #pragma unroll
            for (int rr = 0; rr < 4; rr++)
                bf[rr] = __ldg(src + (size_t)(g * 4 + rr) * CDIM);   // coalesced across c
            const uint32_t half = (uint32_t)(g >> 3);
            const uint32_t gsl  = ((uint32_t)(g & 7)) ^ csw;
            *(float4*)(sb + half * (uint32_t)OFF_B + ((uint32_t)c << 7) + (gsl << 4)) = buf;
        }
    }
    __syncthreads();

    // ---- layer-1 GEMM, thread tile = 8 rows x 8 cols; W1 streamed via cp.async ----
    const int lane = tid & 31;
    const int wid  = tid >> 5;
    const int rb   = lane & 7;                  // rows rb*8 .. rb*8+7
    const int e    = lane >> 3;                 // 0..3
    const int j0   = (wid * 4 + e) * 8;         // output col base

    unsigned long long acc[4][8];               // [rowpair][col]
    {
        const float4 b1a = __ldg((const float4*)(b1 + j0));
        const float4 b1b = __ldg((const float4*)(b1 + j0 + 4));
        #pragma unroll
        for (int rp = 0; rp < 4; rp++) {
            acc[rp][0] = pack2(b1a.x, b1a.x); acc[rp][1] = pack2(b1a.y, b1a.y);
            acc[rp][2] = pack2(b1a.z, b1a.z); acc[rp][3] = pack2(b1a.w, b1a.w);
            acc[rp][4] = pack2(b1b.x, b1b.x); acc[rp][5] = pack2(b1b.y, b1b.y);
            acc[rp][6] = pack2(b1b.z, b1b.z); acc[rp][7] = pack2(b1b.w, b1b.w);
        }
    }

    const char* ebase = sb + (uint32_t)(rb >> 2) * (uint32_t)OFF_B;
    const uint32_t rbf = ((uint32_t)(rb & 3)) << 5;
    const uint32_t wlane = ((uint32_t)wid << 7) + ((uint32_t)e << 5);   // per-thread W1 col offset

    #pragma unroll 1
    for (int blk = 0; blk < NBLK; blk++) {
        asm volatile("cp.async.wait_group 0;" ::: "memory");
        __syncthreads();    // block data visible; all reads of the other slot finished

        if (blk < NBLK - 1) {
            const float* src = W1 + (size_t)(blk + 1) * WBLK * CDIM;
            const uint32_t dst = w1s + (uint32_t)((blk + 1) & 1) * 16384u;
            #pragma unroll
            for (int i = 0; i < 4; i++)
                asm volatile("cp.async.cg.shared.global [%0], [%1], 16;"
                    :: "r"(dst + (uint32_t)(tid + i * 256) * 16u),
                       "l"(src + (size_t)(tid + i * 256) * 4) : "memory");
            asm volatile("cp.async.commit_group;" ::: "memory");
        }

        const char* wb = sb + OFF_W1 + ((uint32_t)(blk & 1)) * 16384u;
        #pragma unroll
        for (int cc = 0; cc < WBLK; cc++) {
            const int c = blk * WBLK + cc;
            const float4 wA = *(const float4*)(wb + (uint32_t)cc * 1024u + wlane);
            const float4 wB = *(const float4*)(wb + (uint32_t)cc * 1024u + wlane + 16u);
            const uint32_t v0 = rbf ^ ((uint32_t)(c & 7) << 4);
            const char* ep = ebase + ((uint32_t)c << 7);
            const ulonglong2 eA = *(const ulonglong2*)(ep + v0);
            const ulonglong2 eB = *(const ulonglong2*)(ep + (v0 ^ 16u));
            const unsigned long long w0 = pack2(wA.x, wA.x);
            const unsigned long long w1v = pack2(wA.y, wA.y);
            const unsigned long long w2v = pack2(wA.z, wA.z);
            const unsigned long long w3 = pack2(wA.w, wA.w);
            const unsigned long long w4 = pack2(wB.x, wB.x);
            const unsigned long long w5 = pack2(wB.y, wB.y);
            const unsigned long long w6 = pack2(wB.z, wB.z);
            const unsigned long long w7 = pack2(wB.w, wB.w);
            acc[0][0] = ffma2(eA.x, w0, acc[0][0]); acc[0][1] = ffma2(eA.x, w1v, acc[0][1]);
            acc[0][2] = ffma2(eA.x, w2v, acc[0][2]); acc[0][3] = ffma2(eA.x, w3, acc[0][3]);
            acc[0][4] = ffma2(eA.x, w4, acc[0][4]); acc[0][5] = ffma2(eA.x, w5, acc[0][5]);
            acc[0][6] = ffma2(eA.x, w6, acc[0][6]); acc[0][7] = ffma2(eA.x, w7, acc[0][7]);
            acc[1][0] = ffma2(eA.y, w0, acc[1][0]); acc[1][1] = ffma2(eA.y, w1v, acc[1][1]);
            acc[1][2] = ffma2(eA.y, w2v, acc[1][2]); acc[1][3] = ffma2(eA.y, w3, acc[1][3]);
            acc[1][4] = ffma2(eA.y, w4, acc[1][4]); acc[1][5] = ffma2(eA.y, w5, acc[1][5]);
            acc[1][6] = ffma2(eA.y, w6, acc[1][6]); acc[1][7] = ffma2(eA.y, w7, acc[1][7]);
            acc[2][0] = ffma2(eB.x, w0, acc[2][0]); acc[2][1] = ffma2(eB.x, w1v, acc[2][1]);
            acc[2][2] = ffma2(eB.x, w2v, acc[2][2]); acc[2][3] = ffma2(eB.x, w3, acc[2][3]);
            acc[2][4] = ffma2(eB.x, w4, acc[2][4]); acc[2][5] = ffma2(eB.x, w5, acc[2][5]);
            acc[2][6] = ffma2(eB.x, w6, acc[2][6]); acc[2][7] = ffma2(eB.x, w7, acc[2][7]);
            acc[3][0] = ffma2(eB.y, w0, acc[3][0]); acc[3][1] = ffma2(eB.y, w1v, acc[3][1]);
            acc[3][2] = ffma2(eB.y, w2v, acc[3][2]); acc[3][3] = ffma2(eB.y, w3, acc[3][3]);
            acc[3][4] = ffma2(eB.y, w4, acc[3][4]); acc[3][5] = ffma2(eB.y, w5, acc[3][5]);
            acc[3][6] = ffma2(eB.y, w6, acc[3][6]); acc[3][7] = ffma2(eB.y, w7, acc[3][7]);
        }
    }

    __syncthreads();   // emb reads complete before buffer reuse as h

    // ---- tanh + store h ----
    {
        #pragma unroll
        for (int rp = 0; rp < 4; rp++) {
            float lo[8], hi[8];
            #pragma unroll
            for (int kk = 0; kk < 8; kk++) unpack2(acc[rp][kk], lo[kk], hi[kk]);
            #pragma unroll
            for (int t = 0; t < 2; t++) {
                const float* v = t ? hi : lo;
                const int row = rb * 8 + 2 * rp + t;
                char* hb = sb + (((uint32_t)row & 31u) << 10)
                              + ((uint32_t)(row >> 5)) * (uint32_t)OFF_B;
                const uint32_t sw = ((uint32_t)(row & 7)) << 4;
                *(float4*)(hb + (((uint32_t)(j0 * 4)) ^ sw)) =
                    make_float4(tanh_fast(v[0]), tanh_fast(v[1]),
                                tanh_fast(v[2]), tanh_fast(v[3]));
                *(float4*)(hb + (((uint32_t)(j0 * 4 + 16)) ^ sw)) =
                    make_float4(tanh_fast(v[4]), tanh_fast(v[5]),
                                tanh_fast(v[6]), tanh_fast(v[7]));
            }
        }
    }
    __syncthreads();

    // ---- layer 2 + tanh epilogue (thread = (row, p)) ----
    {
        const int r = tid >> 2;            // 0..63
        const int p = tid & 3;             // 0..3
        const char* hrow = sb + (((uint32_t)r & 31u) << 10)
                              + ((uint32_t)(r >> 5)) * (uint32_t)OFF_B;
        const uint32_t sw = ((uint32_t)(r & 7)) << 4;
        const char* w2p = sb + OFF_W2T + p * 1040;

        unsigned long long a0 = 0, a1 = 0;
        #pragma unroll 8
        for (int g = 0; g < 64; g++) {
            const uint32_t off = (uint32_t)g << 4;
            const ulonglong2 hv = *(const ulonglong2*)(hrow + (off ^ sw));
            const ulonglong2 wv = *(const ulonglong2*)(w2p + off);
            a0 = ffma2(hv.x, wv.x, a0);
            a1 = ffma2(hv.y, wv.y, a1);
        }
        float l0, h0, l1, h1;
        unpack2(a0, l0, h0);
        unpack2(a1, l1, h1);
        float sum = (l0 + h0) + (l1 + h1) + __ldg(b2 + p);
        const float off = 0.077f * tanh_fast(sum);
        const float2 spt = ((const float2*)(sb + OFF_SPT))[r];
        const int gr = bid * ROWS + r;
        out[(size_t)gr * 4 + p] = off + ((p & 1) ? spt.y : spt.x);
    }
}

extern "C" void kernel_launch(void* const* d_in, const int* in_sizes, int n_in,
                              void* d_out, int out_size)
{
    const float* ref_polys  = (const float*)d_in[0];
    const int*   ref_levels = (const int*)  d_in[1];
    const float* memory     = (const float*)d_in[2];
    const float* W1         = (const float*)d_in[3];
    const float* b1         = (const float*)d_in[4];
    const float* W2         = (const float*)d_in[5];
    const float* b2         = (const float*)d_in[6];
    float* out = (float*)d_out;

    cudaFuncSetAttribute(decoder_gemm_kernel,
                         cudaFuncAttributeMaxDynamicSharedMemorySize, SMEM_TOTAL);

    gather_kernel<<<NROWS_TOTAL / 4, 256>>>(ref_polys, ref_levels, memory);
    decoder_gemm_kernel<<<NCTAS, 256, SMEM_TOTAL>>>(ref_polys, W1, b1, W2, b2, out);
}